// round 12
// baseline (speedup 1.0000x reference)
#include <cuda_runtime.h>
#include <cfloat>
#include <climits>

#define VOCAB 30522
#define CAND_CAP (1 << 20)
#define OVF_CAP  (1 << 18)
#define TOPK 10
#define NB1 296
#define STAGE_CAP 2048

// ---- device scratch (BSS zero-init; every launch restores the invariant) ----
__device__ float g_scores[500000];
__device__ int   g_cand_doc[CAND_CAP];
__device__ int   g_ncand;          // reset by topk last block
__device__ int   g_ovf_pos[OVF_CAP];
__device__ float g_ovf_val[OVF_CAP];
__device__ int   g_novf;           // reset by topk last block
__device__ int   g_done;           // score CTA ticket, reset by topk last block
__device__ int   g_tk_done;        // topk block ticket, reset by topk last block
__device__ float g_blk_v[NB1 * TOPK];
__device__ int   g_blk_i[NB1 * TOPK];

// ---------------------------------------------------------------------------
// score_fused: stream nnz with 8x-batched int4 loads (MLP=8), plain smem qtab
// lookup (1 LDS + FSETP + rare branch), CTA-local hit staging + per-CTA
// resolve; tiny global spill on overflow, resolved by last-finishing CTA.
// ---------------------------------------------------------------------------
__global__ void __launch_bounds__(1024, 1)
score_kernel(const int* __restrict__ qidx, const float* __restrict__ qval, int qn,
             const int* __restrict__ indice, const float* __restrict__ values,
             const int* __restrict__ crow, int n_docs, int nnz)
{
    extern __shared__ float qtab[];   // VOCAB floats = 122088 B
    __shared__ int   sc_cnt;
    __shared__ int   sc_pos[STAGE_CAP];
    __shared__ float sc_val[STAGE_CAP];
    __shared__ int   cd_cnt;
    __shared__ int   cd_doc[STAGE_CAP];
    __shared__ int   cd_base, cd_flush;
    __shared__ int   s_last;

    for (int i = threadIdx.x; i < VOCAB; i += 1024) qtab[i] = 0.0f;
    if (threadIdx.x == 0) { sc_cnt = 0; cd_cnt = 0; }
    __syncthreads();
    if (threadIdx.x < qn) atomicAdd(&qtab[qidx[threadIdx.x]], qval[threadIdx.x]);
    __syncthreads();

    const int gtid = blockIdx.x * 1024 + threadIdx.x;
    const int gsz  = gridDim.x * 1024;
    const int total4 = nnz >> 2;
    const int4* __restrict__ ind4 = (const int4*)indice;

    #define EMIT(e, jj)                                                        \
        {                                                                      \
            float q = qtab[e];                                                 \
            if (q != 0.0f) {                                                   \
                float v = q * __ldg(values + (jj));                            \
                int p = atomicAdd(&sc_cnt, 1);                                 \
                if (p < STAGE_CAP) { sc_pos[p] = (jj); sc_val[p] = v; }        \
                else {                                                         \
                    int gp = atomicAdd(&g_novf, 1);                            \
                    if (gp < OVF_CAP) {                                        \
                        g_ovf_pos[gp] = (jj); g_ovf_val[gp] = v;               \
                    }                                                          \
                }                                                              \
            }                                                                  \
        }
    #define EMIT4(t, jj) EMIT((t).x, jj) EMIT((t).y, (jj) + 1) \
                         EMIT((t).z, (jj) + 2) EMIT((t).w, (jj) + 3)

    int i = gtid;
    // 8x batch: all LDGs issued before any LDS consume -> MLP 8
    for (; i + 7 * gsz < total4; i += 8 * gsz) {
        int4 a0 = __ldcs(ind4 + i);
        int4 a1 = __ldcs(ind4 + i + gsz);
        int4 a2 = __ldcs(ind4 + i + 2 * gsz);
        int4 a3 = __ldcs(ind4 + i + 3 * gsz);
        int4 a4 = __ldcs(ind4 + i + 4 * gsz);
        int4 a5 = __ldcs(ind4 + i + 5 * gsz);
        int4 a6 = __ldcs(ind4 + i + 6 * gsz);
        int4 a7 = __ldcs(ind4 + i + 7 * gsz);

        EMIT4(a0, (i) << 2)
        EMIT4(a1, (i + gsz) << 2)
        EMIT4(a2, (i + 2 * gsz) << 2)
        EMIT4(a3, (i + 3 * gsz) << 2)
        EMIT4(a4, (i + 4 * gsz) << 2)
        EMIT4(a5, (i + 5 * gsz) << 2)
        EMIT4(a6, (i + 6 * gsz) << 2)
        EMIT4(a7, (i + 7 * gsz) << 2)
    }
    for (; i < total4; i += gsz) {
        int4 a = __ldcs(ind4 + i);
        EMIT4(a, i << 2)
    }
    int jt = (total4 << 2) + gtid;
    if (jt < nnz) {
        int e = indice[jt];
        EMIT(e, jt)
    }
    #undef EMIT4
    #undef EMIT

    // ---- per-CTA resolve of staged hits (parallel binary searches) ----
    __syncthreads();
    int nh = sc_cnt; if (nh > STAGE_CAP) nh = STAGE_CAP;
    for (int t = threadIdx.x; t < nh; t += 1024) {
        int j = sc_pos[t];
        int lo = 0, hi = n_docs;
        while (lo < hi) {
            int mid = (lo + hi + 1) >> 1;
            if (crow[mid] <= j) lo = mid; else hi = mid - 1;
        }
        float old = atomicAdd(&g_scores[lo], sc_val[t]);
        if (old == 0.0f) {
            int p = atomicAdd(&cd_cnt, 1);
            if (p < STAGE_CAP) cd_doc[p] = lo;
            else {
                int gp = atomicAdd(&g_ncand, 1);
                if (gp < CAND_CAP) g_cand_doc[gp] = lo;
            }
        }
    }

    // ---- flush candidates: ONE global atomic per CTA ----
    __syncthreads();
    if (threadIdx.x == 0) {
        int c = cd_cnt; if (c > STAGE_CAP) c = STAGE_CAP;
        int base = atomicAdd(&g_ncand, c);
        if (base + c > CAND_CAP) c = (base < CAND_CAP) ? (CAND_CAP - base) : 0;
        cd_base = base; cd_flush = c;
    }
    __syncthreads();
    for (int t = threadIdx.x; t < cd_flush; t += 1024)
        g_cand_doc[cd_base + t] = cd_doc[t];

    // ---- last-finishing CTA resolves the (rare) overflow spill ----
    __threadfence();
    if (threadIdx.x == 0)
        s_last = (atomicAdd(&g_done, 1) == gridDim.x - 1) ? 1 : 0;
    __syncthreads();
    if (s_last) {
        __threadfence();
        int no = g_novf; if (no > OVF_CAP) no = OVF_CAP;
        for (int t = threadIdx.x; t < no; t += 1024) {
            int j = g_ovf_pos[t];
            int lo = 0, hi = n_docs;
            while (lo < hi) {
                int mid = (lo + hi + 1) >> 1;
                if (crow[mid] <= j) lo = mid; else hi = mid - 1;
            }
            float old = atomicAdd(&g_scores[lo], g_ovf_val[t]);
            if (old == 0.0f) {
                int gp = atomicAdd(&g_ncand, 1);
                if (gp < CAND_CAP) g_cand_doc[gp] = lo;
            }
        }
    }
}

// ---------------------------------------------------------------------------
// top-k helpers (static register indexing only)
// ---------------------------------------------------------------------------
__device__ __forceinline__ void insert10(float* lv, int* li, float s, int d) {
    if (s > lv[TOPK - 1] || (s == lv[TOPK - 1] && d < li[TOPK - 1])) {
        lv[TOPK - 1] = s; li[TOPK - 1] = d;
        #pragma unroll
        for (int k = TOPK - 1; k > 0; k--) {
            bool sw = (lv[k] > lv[k - 1]) ||
                      (lv[k] == lv[k - 1] && li[k] < li[k - 1]);
            if (sw) {
                float tv = lv[k]; lv[k] = lv[k - 1]; lv[k - 1] = tv;
                int   ti = li[k]; li[k] = li[k - 1]; li[k - 1] = ti;
            }
        }
    }
}

__device__ __forceinline__ void warp_merge10(float* lv, int* li,
                                             float* out_v, int* out_i) {
    int lane = threadIdx.x & 31;
    #pragma unroll
    for (int r = 0; r < TOPK; r++) {
        float bv = lv[0]; int bi = li[0]; int bl = lane;
        #pragma unroll
        for (int off = 16; off; off >>= 1) {
            float ov = __shfl_down_sync(0xffffffffu, bv, off);
            int   oi = __shfl_down_sync(0xffffffffu, bi, off);
            int   ol = __shfl_down_sync(0xffffffffu, bl, off);
            if (ov > bv || (ov == bv && oi < bi)) { bv = ov; bi = oi; bl = ol; }
        }
        bl = __shfl_sync(0xffffffffu, bl, 0);
        float wv = __shfl_sync(0xffffffffu, bv, 0);
        int   wi = __shfl_sync(0xffffffffu, bi, 0);
        if (lane == bl) {
            #pragma unroll
            for (int k = 0; k < TOPK - 1; k++) { lv[k] = lv[k + 1]; li[k] = li[k + 1]; }
            lv[TOPK - 1] = -FLT_MAX; li[TOPK - 1] = INT_MAX;
        }
        if (lane == 0) { out_v[r] = wv; out_i[r] = wi; }
    }
}

__device__ __forceinline__ void block_merge10(const float* sv, const int* si,
                                              int nwarp, float* out_v, int* out_i) {
    int lane = threadIdx.x & 31;
    float lv[TOPK]; int li[TOPK];
    #pragma unroll
    for (int k = 0; k < TOPK; k++) {
        if (lane < nwarp) { lv[k] = sv[lane * TOPK + k]; li[k] = si[lane * TOPK + k]; }
        else              { lv[k] = -FLT_MAX;            li[k] = INT_MAX;            }
    }
    warp_merge10(lv, li, out_v, out_i);
}

// ---------------------------------------------------------------------------
// top-k (single kernel): per-block scan of candidates with fused cleanup,
// block winners to global; LAST-finishing block merges all winners, writes
// output, resets counters. out layout: [TOPK values][TOPK indices-as-float]
// ---------------------------------------------------------------------------
__global__ void __launch_bounds__(256)
topk_kernel(float* __restrict__ out, int out_size) {
    __shared__ float sv[8 * TOPK];
    __shared__ int   si[8 * TOPK];
    __shared__ int   s_last;

    float lv[TOPK]; int li[TOPK];
    #pragma unroll
    for (int k = 0; k < TOPK; k++) { lv[k] = -FLT_MAX; li[k] = INT_MAX; }

    int nc = g_ncand;
    if (nc > CAND_CAP) nc = CAND_CAP;
    int gtid = blockIdx.x * blockDim.x + threadIdx.x;
    int gsz  = gridDim.x * blockDim.x;

    int t = gtid;
    for (; t + 3 * gsz < nc; t += 4 * gsz) {
        int d0 = g_cand_doc[t];
        int d1 = g_cand_doc[t + gsz];
        int d2 = g_cand_doc[t + 2 * gsz];
        int d3 = g_cand_doc[t + 3 * gsz];
        float s0 = g_scores[d0];
        float s1 = g_scores[d1];
        float s2 = g_scores[d2];
        float s3 = g_scores[d3];
        g_scores[d0] = 0.0f;
        g_scores[d1] = 0.0f;
        g_scores[d2] = 0.0f;
        g_scores[d3] = 0.0f;
        insert10(lv, li, s0, d0);
        insert10(lv, li, s1, d1);
        insert10(lv, li, s2, d2);
        insert10(lv, li, s3, d3);
    }
    for (; t < nc; t += gsz) {
        int d = g_cand_doc[t];
        float s = g_scores[d];
        g_scores[d] = 0.0f;
        insert10(lv, li, s, d);
    }

    int wid = threadIdx.x >> 5;
    warp_merge10(lv, li, sv + wid * TOPK, si + wid * TOPK);
    __syncthreads();
    if (wid == 0)
        block_merge10(sv, si, 8, g_blk_v + blockIdx.x * TOPK,
                      g_blk_i + blockIdx.x * TOPK);

    // ---- last-finishing block performs the final merge ----
    __threadfence();
    __syncthreads();
    if (threadIdx.x == 0)
        s_last = (atomicAdd(&g_tk_done, 1) == gridDim.x - 1) ? 1 : 0;
    __syncthreads();
    if (!s_last) return;
    __threadfence();

    const int NC = NB1 * TOPK;
    #pragma unroll
    for (int k = 0; k < TOPK; k++) { lv[k] = -FLT_MAX; li[k] = INT_MAX; }
    for (int p = threadIdx.x; p < NC; p += 256)
        insert10(lv, li, g_blk_v[p], g_blk_i[p]);

    __syncthreads();   // reuse sv/si
    warp_merge10(lv, li, sv + wid * TOPK, si + wid * TOPK);
    __syncthreads();
    __shared__ float fv[TOPK];
    __shared__ int   fi[TOPK];
    if (wid == 0) block_merge10(sv, si, 8, fv, fi);
    __syncthreads();

    if (threadIdx.x < TOPK) {
        int k = threadIdx.x;
        if (k < out_size) out[k] = fv[k];
        if (TOPK + k < out_size) out[TOPK + k] = (float)fi[k];
    }
    if (threadIdx.x == 0) {   // reset all counters for next graph replay
        g_ncand = 0;
        g_novf = 0;
        g_done = 0;
        g_tk_done = 0;
    }
}

// ---------------------------------------------------------------------------
// kernel_launch
// Inputs: q_indices(i32,32) q_values(f32,32) crow(i32,N+1) indice(i32,nnz)
//         values(f32,nnz) [top_k]
// ---------------------------------------------------------------------------
extern "C" void kernel_launch(void* const* d_in, const int* in_sizes, int n_in,
                              void* d_out, int out_size) {
    const int*   qidx   = (const int*)d_in[0];
    const float* qval   = (const float*)d_in[1];
    const int*   crow   = (const int*)d_in[2];
    const int*   indice = (const int*)d_in[3];
    const float* values = (const float*)d_in[4];

    int qn     = in_sizes[0];
    int n_docs = in_sizes[2] - 1;
    int nnz    = in_sizes[3];

    const int SMEM_Q = VOCAB * (int)sizeof(float);
    cudaFuncSetAttribute(score_kernel, cudaFuncAttributeMaxDynamicSharedMemorySize, SMEM_Q);

    score_kernel<<<148, 1024, SMEM_Q>>>(qidx, qval, qn, indice, values,
                                        crow, n_docs, nnz);
    topk_kernel<<<NB1, 256>>>((float*)d_out, out_size);
}

// round 13
// speedup vs baseline: 1.4202x; 1.4202x over previous
#include <cuda_runtime.h>
#include <cfloat>
#include <climits>

#define VOCAB 30522
#define CAND_CAP (1 << 20)
#define OVF_CAP  (1 << 18)
#define TOPK 10
#define NB1 296
#define STAGE_CAP 2048

// ---- device scratch (BSS zero-init; every launch restores the invariant) ----
__device__ float g_scores[500000];
__device__ int   g_cand_doc[CAND_CAP];
__device__ int   g_ncand;          // reset by topk last block
__device__ int   g_ovf_pos[OVF_CAP];
__device__ float g_ovf_val[OVF_CAP];
__device__ int   g_novf;           // reset by topk last block
__device__ int   g_done;           // score CTA ticket, reset by topk last block
__device__ int   g_tk_done;        // topk block ticket, reset by topk last block
__device__ float g_blk_v[NB1 * TOPK];
__device__ int   g_blk_i[NB1 * TOPK];

// ---------------------------------------------------------------------------
// score_fused: stream nnz (4x-batched int4 -> MLP>=4; 8x exceeded the 64-reg
// budget at 1024 thr), plain smem qtab lookup, CTA-local hit staging +
// per-CTA resolve. Fences are thread-0-only after __syncthreads (cumulative
// fence pattern) -- one MEMBAR per CTA, not per thread.
// ---------------------------------------------------------------------------
__global__ void __launch_bounds__(1024, 1)
score_kernel(const int* __restrict__ qidx, const float* __restrict__ qval, int qn,
             const int* __restrict__ indice, const float* __restrict__ values,
             const int* __restrict__ crow, int n_docs, int nnz)
{
    extern __shared__ float qtab[];   // VOCAB floats = 122088 B
    __shared__ int   sc_cnt;
    __shared__ int   sc_pos[STAGE_CAP];
    __shared__ float sc_val[STAGE_CAP];
    __shared__ int   cd_cnt;
    __shared__ int   cd_doc[STAGE_CAP];
    __shared__ int   cd_base, cd_flush;
    __shared__ int   s_last;

    for (int i = threadIdx.x; i < VOCAB; i += 1024) qtab[i] = 0.0f;
    if (threadIdx.x == 0) { sc_cnt = 0; cd_cnt = 0; }
    __syncthreads();
    if (threadIdx.x < qn) atomicAdd(&qtab[qidx[threadIdx.x]], qval[threadIdx.x]);
    __syncthreads();

    const int gtid = blockIdx.x * 1024 + threadIdx.x;
    const int gsz  = gridDim.x * 1024;
    const int total4 = nnz >> 2;
    const int4* __restrict__ ind4 = (const int4*)indice;

    #define EMIT(e, jj)                                                        \
        {                                                                      \
            float q = qtab[e];                                                 \
            if (q != 0.0f) {                                                   \
                float v = q * __ldg(values + (jj));                            \
                int p = atomicAdd(&sc_cnt, 1);                                 \
                if (p < STAGE_CAP) { sc_pos[p] = (jj); sc_val[p] = v; }        \
                else {                                                         \
                    int gp = atomicAdd(&g_novf, 1);                            \
                    if (gp < OVF_CAP) {                                        \
                        g_ovf_pos[gp] = (jj); g_ovf_val[gp] = v;               \
                    }                                                          \
                }                                                              \
            }                                                                  \
        }
    #define EMIT4(t, jj) EMIT((t).x, jj) EMIT((t).y, (jj) + 1) \
                         EMIT((t).z, (jj) + 2) EMIT((t).w, (jj) + 3)

    int i = gtid;
    for (; i + 3 * gsz < total4; i += 4 * gsz) {
        int4 a = __ldcs(ind4 + i);
        int4 b = __ldcs(ind4 + i + gsz);
        int4 c = __ldcs(ind4 + i + 2 * gsz);
        int4 d = __ldcs(ind4 + i + 3 * gsz);

        EMIT4(a, (i) << 2)
        EMIT4(b, (i + gsz) << 2)
        EMIT4(c, (i + 2 * gsz) << 2)
        EMIT4(d, (i + 3 * gsz) << 2)
    }
    for (; i < total4; i += gsz) {
        int4 a = __ldcs(ind4 + i);
        EMIT4(a, i << 2)
    }
    int jt = (total4 << 2) + gtid;
    if (jt < nnz) {
        int e = indice[jt];
        EMIT(e, jt)
    }
    #undef EMIT4
    #undef EMIT

    // ---- per-CTA resolve of staged hits (parallel binary searches) ----
    __syncthreads();
    int nh = sc_cnt; if (nh > STAGE_CAP) nh = STAGE_CAP;
    for (int t = threadIdx.x; t < nh; t += 1024) {
        int j = sc_pos[t];
        int lo = 0, hi = n_docs;
        while (lo < hi) {
            int mid = (lo + hi + 1) >> 1;
            if (crow[mid] <= j) lo = mid; else hi = mid - 1;
        }
        float old = atomicAdd(&g_scores[lo], sc_val[t]);
        if (old == 0.0f) {
            int p = atomicAdd(&cd_cnt, 1);
            if (p < STAGE_CAP) cd_doc[p] = lo;
            else {
                int gp = atomicAdd(&g_ncand, 1);
                if (gp < CAND_CAP) g_cand_doc[gp] = lo;
            }
        }
    }

    // ---- flush candidates: ONE global atomic per CTA ----
    __syncthreads();
    if (threadIdx.x == 0) {
        int c = cd_cnt; if (c > STAGE_CAP) c = STAGE_CAP;
        int base = atomicAdd(&g_ncand, c);
        if (base + c > CAND_CAP) c = (base < CAND_CAP) ? (CAND_CAP - base) : 0;
        cd_base = base; cd_flush = c;
    }
    __syncthreads();
    for (int t = threadIdx.x; t < cd_flush; t += 1024)
        g_cand_doc[cd_base + t] = cd_doc[t];

    // ---- completion ticket: t0-only cumulative fence (release+acquire) ----
    __syncthreads();
    if (threadIdx.x == 0) {
        __threadfence();                        // release block's writes
        s_last = (atomicAdd(&g_done, 1) == gridDim.x - 1) ? 1 : 0;
        if (s_last) __threadfence();            // acquire others' writes
    }
    __syncthreads();
    if (s_last) {
        int no = g_novf; if (no > OVF_CAP) no = OVF_CAP;
        for (int t = threadIdx.x; t < no; t += 1024) {
            int j = g_ovf_pos[t];
            int lo = 0, hi = n_docs;
            while (lo < hi) {
                int mid = (lo + hi + 1) >> 1;
                if (crow[mid] <= j) lo = mid; else hi = mid - 1;
            }
            float old = atomicAdd(&g_scores[lo], g_ovf_val[t]);
            if (old == 0.0f) {
                int gp = atomicAdd(&g_ncand, 1);
                if (gp < CAND_CAP) g_cand_doc[gp] = lo;
            }
        }
    }
}

// ---------------------------------------------------------------------------
// top-k helpers (static register indexing only)
// ---------------------------------------------------------------------------
__device__ __forceinline__ void insert10(float* lv, int* li, float s, int d) {
    if (s > lv[TOPK - 1] || (s == lv[TOPK - 1] && d < li[TOPK - 1])) {
        lv[TOPK - 1] = s; li[TOPK - 1] = d;
        #pragma unroll
        for (int k = TOPK - 1; k > 0; k--) {
            bool sw = (lv[k] > lv[k - 1]) ||
                      (lv[k] == lv[k - 1] && li[k] < li[k - 1]);
            if (sw) {
                float tv = lv[k]; lv[k] = lv[k - 1]; lv[k - 1] = tv;
                int   ti = li[k]; li[k] = li[k - 1]; li[k - 1] = ti;
            }
        }
    }
}

__device__ __forceinline__ void warp_merge10(float* lv, int* li,
                                             float* out_v, int* out_i) {
    int lane = threadIdx.x & 31;
    #pragma unroll
    for (int r = 0; r < TOPK; r++) {
        float bv = lv[0]; int bi = li[0]; int bl = lane;
        #pragma unroll
        for (int off = 16; off; off >>= 1) {
            float ov = __shfl_down_sync(0xffffffffu, bv, off);
            int   oi = __shfl_down_sync(0xffffffffu, bi, off);
            int   ol = __shfl_down_sync(0xffffffffu, bl, off);
            if (ov > bv || (ov == bv && oi < bi)) { bv = ov; bi = oi; bl = ol; }
        }
        bl = __shfl_sync(0xffffffffu, bl, 0);
        float wv = __shfl_sync(0xffffffffu, bv, 0);
        int   wi = __shfl_sync(0xffffffffu, bi, 0);
        if (lane == bl) {
            #pragma unroll
            for (int k = 0; k < TOPK - 1; k++) { lv[k] = lv[k + 1]; li[k] = li[k + 1]; }
            lv[TOPK - 1] = -FLT_MAX; li[TOPK - 1] = INT_MAX;
        }
        if (lane == 0) { out_v[r] = wv; out_i[r] = wi; }
    }
}

__device__ __forceinline__ void block_merge10(const float* sv, const int* si,
                                              int nwarp, float* out_v, int* out_i) {
    int lane = threadIdx.x & 31;
    float lv[TOPK]; int li[TOPK];
    #pragma unroll
    for (int k = 0; k < TOPK; k++) {
        if (lane < nwarp) { lv[k] = sv[lane * TOPK + k]; li[k] = si[lane * TOPK + k]; }
        else              { lv[k] = -FLT_MAX;            li[k] = INT_MAX;            }
    }
    warp_merge10(lv, li, out_v, out_i);
}

// ---------------------------------------------------------------------------
// top-k (single kernel): per-block candidate scan with fused cleanup, block
// winners to global; last-finishing block (t0-only cumulative fence ticket)
// merges winners, writes output, resets counters.
// out layout: [TOPK values][TOPK indices-as-float]
// ---------------------------------------------------------------------------
__global__ void __launch_bounds__(256)
topk_kernel(float* __restrict__ out, int out_size) {
    __shared__ float sv[8 * TOPK];
    __shared__ int   si[8 * TOPK];
    __shared__ int   s_last;

    float lv[TOPK]; int li[TOPK];
    #pragma unroll
    for (int k = 0; k < TOPK; k++) { lv[k] = -FLT_MAX; li[k] = INT_MAX; }

    int nc = g_ncand;
    if (nc > CAND_CAP) nc = CAND_CAP;
    int gtid = blockIdx.x * blockDim.x + threadIdx.x;
    int gsz  = gridDim.x * blockDim.x;

    int t = gtid;
    for (; t + 3 * gsz < nc; t += 4 * gsz) {
        int d0 = g_cand_doc[t];
        int d1 = g_cand_doc[t + gsz];
        int d2 = g_cand_doc[t + 2 * gsz];
        int d3 = g_cand_doc[t + 3 * gsz];
        float s0 = g_scores[d0];
        float s1 = g_scores[d1];
        float s2 = g_scores[d2];
        float s3 = g_scores[d3];
        g_scores[d0] = 0.0f;
        g_scores[d1] = 0.0f;
        g_scores[d2] = 0.0f;
        g_scores[d3] = 0.0f;
        insert10(lv, li, s0, d0);
        insert10(lv, li, s1, d1);
        insert10(lv, li, s2, d2);
        insert10(lv, li, s3, d3);
    }
    for (; t < nc; t += gsz) {
        int d = g_cand_doc[t];
        float s = g_scores[d];
        g_scores[d] = 0.0f;
        insert10(lv, li, s, d);
    }

    int wid = threadIdx.x >> 5;
    warp_merge10(lv, li, sv + wid * TOPK, si + wid * TOPK);
    __syncthreads();
    if (wid == 0)
        block_merge10(sv, si, 8, g_blk_v + blockIdx.x * TOPK,
                      g_blk_i + blockIdx.x * TOPK);

    // ---- ticket: t0-only cumulative fence ----
    __syncthreads();
    if (threadIdx.x == 0) {
        __threadfence();                        // release block's writes
        s_last = (atomicAdd(&g_tk_done, 1) == gridDim.x - 1) ? 1 : 0;
        if (s_last) __threadfence();            // acquire others' writes
    }
    __syncthreads();
    if (!s_last) return;

    const int NC = NB1 * TOPK;
    #pragma unroll
    for (int k = 0; k < TOPK; k++) { lv[k] = -FLT_MAX; li[k] = INT_MAX; }
    for (int p = threadIdx.x; p < NC; p += 256)
        insert10(lv, li, g_blk_v[p], g_blk_i[p]);

    __syncthreads();   // reuse sv/si
    warp_merge10(lv, li, sv + wid * TOPK, si + wid * TOPK);
    __syncthreads();
    __shared__ float fv[TOPK];
    __shared__ int   fi[TOPK];
    if (wid == 0) block_merge10(sv, si, 8, fv, fi);
    __syncthreads();

    if (threadIdx.x < TOPK) {
        int k = threadIdx.x;
        if (k < out_size) out[k] = fv[k];
        if (TOPK + k < out_size) out[TOPK + k] = (float)fi[k];
    }
    if (threadIdx.x == 0) {   // reset all counters for next graph replay
        g_ncand = 0;
        g_novf = 0;
        g_done = 0;
        g_tk_done = 0;
    }
}

// ---------------------------------------------------------------------------
// kernel_launch
// Inputs: q_indices(i32,32) q_values(f32,32) crow(i32,N+1) indice(i32,nnz)
//         values(f32,nnz) [top_k]
// ---------------------------------------------------------------------------
extern "C" void kernel_launch(void* const* d_in, const int* in_sizes, int n_in,
                              void* d_out, int out_size) {
    const int*   qidx   = (const int*)d_in[0];
    const float* qval   = (const float*)d_in[1];
    const int*   crow   = (const int*)d_in[2];
    const int*   indice = (const int*)d_in[3];
    const float* values = (const float*)d_in[4];

    int qn     = in_sizes[0];
    int n_docs = in_sizes[2] - 1;
    int nnz    = in_sizes[3];

    const int SMEM_Q = VOCAB * (int)sizeof(float);
    cudaFuncSetAttribute(score_kernel, cudaFuncAttributeMaxDynamicSharedMemorySize, SMEM_Q);

    score_kernel<<<148, 1024, SMEM_Q>>>(qidx, qval, qn, indice, values,
                                        crow, n_docs, nnz);
    topk_kernel<<<NB1, 256>>>((float*)d_out, out_size);
}